// round 1
// baseline (speedup 1.0000x reference)
#include <cuda_runtime.h>
#include <math.h>
#include <stdint.h>

#define T_DIM 2048
#define H_DIM 2048
#define I_DIM 2880
#define E_DIM 8
#define GU_DIM 5760   // 2*I

// ---------------- scratch (static device allocations) ----------------
__device__ __align__(128) float g_gu_shared[(size_t)T_DIM * GU_DIM];     // 47 MB
__device__ __align__(128) float g_gu_routed[(size_t)2 * T_DIM * GU_DIM]; // 94 MB, row = token*2 + slot
__device__ int   g_cnt[E_DIM];
__device__ int   g_pair_tok[E_DIM * T_DIM];
__device__ int   g_pair_gp [E_DIM * T_DIM];
__device__ float g_pair_scale[E_DIM * T_DIM];

// ---------------- tiny kernels ----------------
__global__ void zero_cnt_kernel() {
    if (threadIdx.x < E_DIM) g_cnt[threadIdx.x] = 0;
}

// Router: logits = x @ rw^T  [T, 8]; top-2 -> sigmoid; write router_scores,
// build per-expert compacted pair lists.
__global__ void router_kernel(const float* __restrict__ x,
                              const float* __restrict__ rw,
                              float* __restrict__ out, int writeScores) {
    int t = blockIdx.x * 8 + (threadIdx.x >> 5);
    int lane = threadIdx.x & 31;
    if (t >= T_DIM) return;
    const float* xr = x + (size_t)t * H_DIM;
    float s[E_DIM];
#pragma unroll
    for (int e = 0; e < E_DIM; e++) s[e] = 0.f;
    for (int h = lane; h < H_DIM; h += 32) {
        float xv = xr[h];
#pragma unroll
        for (int e = 0; e < E_DIM; e++) s[e] += xv * rw[e * H_DIM + h];
    }
#pragma unroll
    for (int e = 0; e < E_DIM; e++) {
#pragma unroll
        for (int off = 16; off > 0; off >>= 1)
            s[e] += __shfl_xor_sync(0xffffffffu, s[e], off);
    }
    if (lane == 0) {
        int i1 = 0; float v1 = s[0];
#pragma unroll
        for (int e = 1; e < E_DIM; e++) if (s[e] > v1) { v1 = s[e]; i1 = e; }
        int i2 = -1; float v2 = -INFINITY;
#pragma unroll
        for (int e = 0; e < E_DIM; e++) if (e != i1 && s[e] > v2) { v2 = s[e]; i2 = e; }
        float sg1 = 1.f / (1.f + expf(-v1));
        float sg2 = 1.f / (1.f + expf(-v2));
        if (writeScores) {
            float* rs = out + (size_t)T_DIM * H_DIM;
#pragma unroll
            for (int e = 0; e < E_DIM; e++)
                rs[(size_t)e * T_DIM + t] = (e == i1) ? sg1 : ((e == i2) ? sg2 : 0.f);
        }
        int p1 = atomicAdd(&g_cnt[i1], 1);
        g_pair_tok[i1 * T_DIM + p1] = t;
        g_pair_gp [i1 * T_DIM + p1] = t * 2;
        g_pair_scale[i1 * T_DIM + p1] = sg1;
        int p2 = atomicAdd(&g_cnt[i2], 1);
        g_pair_tok[i2 * T_DIM + p2] = t;
        g_pair_gp [i2 * T_DIM + p2] = t * 2 + 1;
        g_pair_scale[i2 * T_DIM + p2] = sg2;
    }
}

// ---------------- generic TF32 GEMM ----------------
#define BM 128
#define BN 128
#define BK 32
#define AST 36                 // padded A smem stride (floats)
#define A_TILE_F (BM * AST)    // 4608 floats per stage
#define B_TILE_F 4608          // per-stage B region (covers both layouts)
#define BNT_ST 36
#define BNN_ST 132
#define SMEM_BYTES ((2 * A_TILE_F + 2 * B_TILE_F) * 4)  // 73728

__device__ __forceinline__ void cpasync16(uint32_t dst, const void* src) {
    asm volatile("cp.async.cg.shared.global [%0], [%1], 16;" :: "r"(dst), "l"(src));
}
__device__ __forceinline__ uint32_t f2tf(float f) {
    uint32_t u;
    asm("cvt.rna.tf32.f32 %0, %1;" : "=r"(u) : "f"(f));
    return u;
}
__device__ __forceinline__ float silu_mul(float g, float u) {
    float s = 1.f / (1.f + expf(-g));
    return u * g * s;
}

// aMode: 0 plain, 1 act(GU), 2 gather, 3 gather+act(GU)
// bMode: 0 NT (B[n][k]), 1 NN (B[k][n]), 2 dual NT (B below dualSplit, B2 above)
// cMode: 0 plain store, 1 scaled store via rowIdxC, 2 atomicAdd via rowIdxC
__global__ void __launch_bounds__(256, 2)
gemm_tf32(const float* __restrict__ A, const float* __restrict__ B,
          const float* __restrict__ B2, float* __restrict__ C,
          int M, int N, int K, int lda, int ldb, int ldc,
          int aMode, int bMode, int cMode, int actOff, int dualSplit,
          const int* __restrict__ rowIdxA, const int* __restrict__ rowIdxC,
          const float* __restrict__ scaleC, const int* __restrict__ cntPtr,
          long long bStride)
{
    extern __shared__ float smem[];
    const int e  = blockIdx.z;
    const int m0 = blockIdx.y * BM;
    const int n0 = blockIdx.x * BN;
    const int mLim = cntPtr ? cntPtr[e] : M;
    if (m0 >= mLim) return;
    const int listBase = e * T_DIM;
    const float* Bp = B + (size_t)e * (size_t)bStride;

    const int tid  = threadIdx.x;
    const int lane = tid & 31, warp = tid >> 5;
    const int wm = (warp & 1) * 64, wn = (warp >> 1) * 32;
    const int gid = lane >> 2, tig = lane & 3;

    float* As = smem;
    float* Bs = smem + 2 * A_TILE_F;
    uint32_t sA = (uint32_t)__cvta_generic_to_shared(As);
    uint32_t sB = (uint32_t)__cvta_generic_to_shared(Bs);

    const bool aAsync = (aMode == 0 || aMode == 2);
    const int numK = K / BK;

    float acc[4][4][4];
#pragma unroll
    for (int a = 0; a < 4; a++)
#pragma unroll
        for (int b = 0; b < 4; b++)
#pragma unroll
            for (int c = 0; c < 4; c++) acc[a][b][c] = 0.f;

    auto loadB = [&](int kt, int st) {
#pragma unroll
        for (int i = 0; i < 4; i++) {
            int cc = tid + i * 256;
            if (bMode == 1) {
                int k = cc >> 5, nc = cc & 31;
                const float* src = Bp + (size_t)(kt * BK + k) * ldb + n0 + nc * 4;
                cpasync16(sB + (st * B_TILE_F + k * BNN_ST + nc * 4) * 4, src);
            } else {
                int n = cc >> 3, kc = cc & 7;
                int gn = n0 + n;
                const float* base = (bMode == 2 && gn >= dualSplit)
                                        ? (B2 + (size_t)(gn - dualSplit) * ldb)
                                        : (Bp + (size_t)gn * ldb);
                cpasync16(sB + (st * B_TILE_F + n * BNT_ST + kc * 4) * 4,
                          base + kt * BK + kc * 4);
            }
        }
    };
    auto loadAasync = [&](int kt, int st) {
#pragma unroll
        for (int i = 0; i < 4; i++) {
            int cc = tid + i * 256;
            int m = cc >> 3, kc = cc & 7;
            int gm;
            if (aMode == 0) gm = m0 + m;
            else { int ml = m0 + m; if (ml >= mLim) ml = mLim - 1; gm = rowIdxA[listBase + ml]; }
            cpasync16(sA + (st * A_TILE_F + m * AST + kc * 4) * 4,
                      A + (size_t)gm * lda + kt * BK + kc * 4);
        }
    };
    auto loadAreg = [&](int kt, float4* pre) {
#pragma unroll
        for (int i = 0; i < 4; i++) {
            int cc = tid + i * 256;
            int m = cc >> 3, kc = cc & 7;
            int gm;
            if (aMode == 1) gm = m0 + m;
            else { int ml = m0 + m; if (ml >= mLim) ml = mLim - 1; gm = rowIdxA[listBase + ml]; }
            const float* p = A + (size_t)gm * lda + kt * BK + kc * 4;
            pre[2 * i]     = *(const float4*)p;
            pre[2 * i + 1] = *(const float4*)(p + actOff);
        }
    };
    auto stsAct = [&](int st, const float4* pre) {
#pragma unroll
        for (int i = 0; i < 4; i++) {
            int cc = tid + i * 256;
            int m = cc >> 3, kc = cc & 7;
            float4 g = pre[2 * i], u = pre[2 * i + 1];
            float4 v;
            v.x = silu_mul(g.x, u.x);
            v.y = silu_mul(g.y, u.y);
            v.z = silu_mul(g.z, u.z);
            v.w = silu_mul(g.w, u.w);
            *(float4*)&As[st * A_TILE_F + m * AST + kc * 4] = v;
        }
    };
    auto compute = [&](int st) {
        const float* Ap_ = As + st * A_TILE_F;
        const float* Bp_ = Bs + st * B_TILE_F;
#pragma unroll
        for (int ks = 0; ks < 4; ks++) {
            const int k0 = ks * 8;
            uint32_t af[4][4];
#pragma unroll
            for (int mt = 0; mt < 4; mt++) {
                int r = wm + mt * 16 + gid;
                af[mt][0] = f2tf(Ap_[r * AST + k0 + tig]);
                af[mt][1] = f2tf(Ap_[(r + 8) * AST + k0 + tig]);
                af[mt][2] = f2tf(Ap_[r * AST + k0 + tig + 4]);
                af[mt][3] = f2tf(Ap_[(r + 8) * AST + k0 + tig + 4]);
            }
            uint32_t bf[4][2];
#pragma unroll
            for (int nt = 0; nt < 4; nt++) {
                int n = wn + nt * 8 + gid;
                if (bMode == 1) {
                    int k = k0 + tig;
                    bf[nt][0] = f2tf(Bp_[k * BNN_ST + n]);
                    bf[nt][1] = f2tf(Bp_[(k + 4) * BNN_ST + n]);
                } else {
                    bf[nt][0] = f2tf(Bp_[n * BNT_ST + k0 + tig]);
                    bf[nt][1] = f2tf(Bp_[n * BNT_ST + k0 + tig + 4]);
                }
            }
#pragma unroll
            for (int mt = 0; mt < 4; mt++)
#pragma unroll
                for (int nt = 0; nt < 4; nt++) {
                    asm volatile(
                        "mma.sync.aligned.m16n8k8.row.col.f32.tf32.tf32.f32 "
                        "{%0,%1,%2,%3}, {%4,%5,%6,%7}, {%8,%9}, {%0,%1,%2,%3};"
                        : "+f"(acc[mt][nt][0]), "+f"(acc[mt][nt][1]),
                          "+f"(acc[mt][nt][2]), "+f"(acc[mt][nt][3])
                        : "r"(af[mt][0]), "r"(af[mt][1]), "r"(af[mt][2]), "r"(af[mt][3]),
                          "r"(bf[nt][0]), "r"(bf[nt][1]));
                }
        }
    };

    // prologue
    float4 pre[8];
    loadB(0, 0);
    if (aAsync) {
        loadAasync(0, 0);
        asm volatile("cp.async.commit_group;");
    } else {
        asm volatile("cp.async.commit_group;");
        loadAreg(0, pre);
        stsAct(0, pre);
    }
    asm volatile("cp.async.wait_group 0;");
    __syncthreads();

    for (int kt = 0; kt < numK; kt++) {
        const int cur = kt & 1, nxt = cur ^ 1;
        const bool hn = (kt + 1) < numK;
        if (hn) {
            loadB(kt + 1, nxt);
            if (aAsync) loadAasync(kt + 1, nxt);
            asm volatile("cp.async.commit_group;");
            if (!aAsync) loadAreg(kt + 1, pre);
        }
        compute(cur);
        if (hn && !aAsync) stsAct(nxt, pre);
        if (hn) asm volatile("cp.async.wait_group 0;");
        __syncthreads();
    }

    // epilogue
#pragma unroll
    for (int mt = 0; mt < 4; mt++) {
#pragma unroll
        for (int rr = 0; rr < 2; rr++) {
            int ml  = wm + mt * 16 + gid + rr * 8;
            int gml = m0 + ml;
            if (gml >= mLim) continue;
            float* crow;
            float sc = 1.f;
            if (cMode == 0) crow = C + (size_t)gml * ldc;
            else {
                int idx = listBase + gml;
                crow = C + (size_t)rowIdxC[idx] * ldc;
                if (cMode == 1) sc = scaleC[idx];
            }
#pragma unroll
            for (int nt = 0; nt < 4; nt++) {
                int cn = n0 + wn + nt * 8 + tig * 2;
                float v0 = acc[mt][nt][rr * 2 + 0] * sc;
                float v1 = acc[mt][nt][rr * 2 + 1] * sc;
                if (cMode == 2) {
                    atomicAdd(crow + cn, v0);
                    atomicAdd(crow + cn + 1, v1);
                } else {
                    *(float2*)(crow + cn) = make_float2(v0, v1);
                }
            }
        }
    }
}

// ---------------- launch ----------------
extern "C" void kernel_launch(void* const* d_in, const int* in_sizes, int n_in,
                              void* d_out, int out_size) {
    const float* x   = (const float*)d_in[0];
    const float* rw  = (const float*)d_in[1];
    const float* gup = (const float*)d_in[2];
    const float* dwn = (const float*)d_in[3];
    const float* sg  = (const float*)d_in[4];
    const float* su  = (const float*)d_in[5];
    const float* sd  = (const float*)d_in[6];
    float* out = (float*)d_out;

    void *p_gu_s, *p_gu_r, *p_tok, *p_gp, *p_scale, *p_cnt;
    cudaGetSymbolAddress(&p_gu_s, g_gu_shared);
    cudaGetSymbolAddress(&p_gu_r, g_gu_routed);
    cudaGetSymbolAddress(&p_tok, g_pair_tok);
    cudaGetSymbolAddress(&p_gp, g_pair_gp);
    cudaGetSymbolAddress(&p_scale, g_pair_scale);
    cudaGetSymbolAddress(&p_cnt, g_cnt);
    float* gu_s = (float*)p_gu_s;
    float* gu_r = (float*)p_gu_r;
    const int* tok = (const int*)p_tok;
    const int* gp  = (const int*)p_gp;
    const float* psc = (const float*)p_scale;
    const int* cnt = (const int*)p_cnt;

    cudaFuncSetAttribute(gemm_tf32, cudaFuncAttributeMaxDynamicSharedMemorySize, SMEM_BYTES);

    int writeScores = (out_size >= T_DIM * H_DIM + E_DIM * T_DIM) ? 1 : 0;

    zero_cnt_kernel<<<1, 32>>>();
    router_kernel<<<T_DIM / 8, 256>>>(x, rw, out, writeScores);

    dim3 blk(256);
    // shared gate+up: GU_s[T, 5760] = x @ [Wg;Wu]^T    (NT dual)
    gemm_tf32<<<dim3(GU_DIM / BN, T_DIM / BM, 1), blk, SMEM_BYTES>>>(
        x, sg, su, gu_s,
        T_DIM, GU_DIM, H_DIM, H_DIM, H_DIM, GU_DIM,
        /*aMode*/0, /*bMode*/2, /*cMode*/0, /*actOff*/0, /*dualSplit*/I_DIM,
        nullptr, nullptr, nullptr, nullptr, 0);

    // shared down: out[T, H] = act(GU_s) @ Wd^T        (NT, act fused in A)
    gemm_tf32<<<dim3(H_DIM / BN, T_DIM / BM, 1), blk, SMEM_BYTES>>>(
        gu_s, sd, nullptr, out,
        T_DIM, H_DIM, I_DIM, GU_DIM, I_DIM, H_DIM,
        /*aMode*/1, /*bMode*/0, /*cMode*/0, /*actOff*/I_DIM, /*dualSplit*/0,
        nullptr, nullptr, nullptr, nullptr, 0);

    // routed gate+up: GU_r[gp, 5760] = s * (x[tok] @ Wgu_e)   (gather A, NN B, scaled scatter C)
    gemm_tf32<<<dim3(GU_DIM / BN, T_DIM / BM, E_DIM), blk, SMEM_BYTES>>>(
        x, gup, nullptr, gu_r,
        T_DIM, GU_DIM, H_DIM, H_DIM, GU_DIM, GU_DIM,
        /*aMode*/2, /*bMode*/1, /*cMode*/1, /*actOff*/0, /*dualSplit*/0,
        tok, gp, psc, cnt, (long long)H_DIM * GU_DIM);

    // routed down: out[tok, H] += act(GU_r[gp]) @ Wd_e        (gather+act A, NN B, atomic C)
    gemm_tf32<<<dim3(H_DIM / BN, T_DIM / BM, E_DIM), blk, SMEM_BYTES>>>(
        gu_r, dwn, nullptr, out,
        T_DIM, H_DIM, I_DIM, GU_DIM, H_DIM, H_DIM,
        /*aMode*/3, /*bMode*/1, /*cMode*/2, /*actOff*/I_DIM, /*dualSplit*/0,
        gp, tok, nullptr, cnt, (long long)I_DIM * H_DIM);
}

// round 4
// speedup vs baseline: 1.3818x; 1.3818x over previous
#include <cuda_runtime.h>
#include <math.h>
#include <stdint.h>

#define T_DIM 2048
#define H_DIM 2048
#define I_DIM 2880
#define E_DIM 8
#define GU_DIM 5760

// ---------------- scratch ----------------
__device__ __align__(128) float g_rx  [(size_t)T_DIM * H_DIM];
__device__ __align__(128) float g_wsgu[(size_t)GU_DIM * H_DIM];
__device__ __align__(128) float g_rsd [(size_t)H_DIM * I_DIM];
__device__ __align__(128) float g_gupT[(size_t)E_DIM * GU_DIM * H_DIM];
__device__ __align__(128) float g_dwnT[(size_t)E_DIM * H_DIM * I_DIM];
__device__ __align__(128) float g_gus [(size_t)T_DIM * GU_DIM];
__device__ __align__(128) float g_acts[(size_t)T_DIM * I_DIM];
__device__ __align__(128) float g_gur [(size_t)2 * T_DIM * GU_DIM];
__device__ __align__(128) float g_actr[(size_t)2 * T_DIM * I_DIM];
__device__ int   g_cnt[E_DIM];
__device__ int   g_ptok[E_DIM * T_DIM];
__device__ int   g_pgp [E_DIM * T_DIM];
__device__ float g_pscl[E_DIM * T_DIM];

// ---------------- helpers ----------------
__device__ __forceinline__ uint32_t f2tf(float f) {
    uint32_t u;
    asm("cvt.rna.tf32.f32 %0, %1;" : "=r"(u) : "f"(f));
    return u;
}
__device__ __forceinline__ float rtf(float f) { return __uint_as_float(f2tf(f)); }
__device__ __forceinline__ void cpasync16(uint32_t dst, const void* src) {
    asm volatile("cp.async.cg.shared.global [%0], [%1], 16;" :: "r"(dst), "l"(src));
}
__device__ __forceinline__ float silu_mul(float g, float u) {
    return u * g / (1.f + expf(-g));
}
// stored position of logical in-group index j (group of 8): [0,4,1,5,2,6,3,7]
__device__ __forceinline__ int permpos(int j) {
    return (j & ~7) | (((j & 3) << 1) | ((j >> 2) & 1));
}

// ---------------- prepass kernels ----------------
// round + k-permute copy (element count multiple of 8)
__global__ void round_perm_copy(const float4* __restrict__ src,
                                float4* __restrict__ dst, long n8) {
    long stride = (long)gridDim.x * blockDim.x;
    for (long g = (long)blockIdx.x * blockDim.x + threadIdx.x; g < n8; g += stride) {
        float4 a = src[g * 2], b = src[g * 2 + 1];
        float4 o0, o1;
        o0.x = rtf(a.x); o0.y = rtf(b.x); o0.z = rtf(a.y); o0.w = rtf(b.y);
        o1.x = rtf(a.z); o1.y = rtf(b.z); o1.z = rtf(a.w); o1.w = rtf(b.w);
        dst[g * 2]     = o0;
        dst[g * 2 + 1] = o1;
    }
}

// dst[e][c][perm(r)] = round(src[e][r][c]); R, C multiples of 32
__global__ void transpose_round_perm(const float* __restrict__ src,
                                     float* __restrict__ dst, int R, int C) {
    __shared__ float ts[32][33];
    size_t eoff = (size_t)blockIdx.z * (size_t)R * C;
    const float* S = src + eoff;
    float* D = dst + eoff;
    int c0 = blockIdx.x * 32, r0 = blockIdx.y * 32;
    int tx = threadIdx.x & 31, ty4 = (threadIdx.x >> 5) * 4;
#pragma unroll
    for (int i = 0; i < 4; i++)
        ts[ty4 + i][tx] = S[(size_t)(r0 + ty4 + i) * C + c0 + tx];
    __syncthreads();
    int pr = permpos(tx);
#pragma unroll
    for (int i = 0; i < 4; i++)
        D[(size_t)(c0 + ty4 + i) * R + r0 + pr] = rtf(ts[tx][ty4 + i]);
}

// act[r][perm(i)] = round(silu(gu[r][i]) * gu[r][I+i])
__global__ void act_perm_kernel(const float* __restrict__ gu,
                                float* __restrict__ dst, int rows) {
    long total = (long)rows * (I_DIM / 8);
    long stride = (long)gridDim.x * blockDim.x;
    for (long idx = (long)blockIdx.x * blockDim.x + threadIdx.x; idx < total; idx += stride) {
        long r = idx / (I_DIM / 8);
        int c = (int)(idx % (I_DIM / 8)) * 8;
        const float* row = gu + r * GU_DIM;
        float4 ga = *(const float4*)(row + c);
        float4 gb = *(const float4*)(row + c + 4);
        float4 ua = *(const float4*)(row + I_DIM + c);
        float4 ub = *(const float4*)(row + I_DIM + c + 4);
        float v0 = rtf(silu_mul(ga.x, ua.x));
        float v1 = rtf(silu_mul(ga.y, ua.y));
        float v2 = rtf(silu_mul(ga.z, ua.z));
        float v3 = rtf(silu_mul(ga.w, ua.w));
        float v4 = rtf(silu_mul(gb.x, ub.x));
        float v5 = rtf(silu_mul(gb.y, ub.y));
        float v6 = rtf(silu_mul(gb.z, ub.z));
        float v7 = rtf(silu_mul(gb.w, ub.w));
        float4 o0, o1;
        o0.x = v0; o0.y = v4; o0.z = v1; o0.w = v5;
        o1.x = v2; o1.y = v6; o1.z = v3; o1.w = v7;
        *(float4*)(dst + r * I_DIM + c)     = o0;
        *(float4*)(dst + r * I_DIM + c + 4) = o1;
    }
}

// ---------------- router ----------------
__global__ void zero_cnt_kernel() {
    if (threadIdx.x < E_DIM) g_cnt[threadIdx.x] = 0;
}

__global__ void router_kernel(const float* __restrict__ x,
                              const float* __restrict__ rw,
                              float* __restrict__ out, int writeScores) {
    int t = blockIdx.x * 8 + (threadIdx.x >> 5);
    int lane = threadIdx.x & 31;
    if (t >= T_DIM) return;
    const float* xr = x + (size_t)t * H_DIM;
    float s[E_DIM];
#pragma unroll
    for (int e = 0; e < E_DIM; e++) s[e] = 0.f;
    for (int h = lane; h < H_DIM; h += 32) {
        float xv = xr[h];
#pragma unroll
        for (int e = 0; e < E_DIM; e++) s[e] += xv * rw[e * H_DIM + h];
    }
#pragma unroll
    for (int e = 0; e < E_DIM; e++) {
#pragma unroll
        for (int off = 16; off > 0; off >>= 1)
            s[e] += __shfl_xor_sync(0xffffffffu, s[e], off);
    }
    if (lane == 0) {
        int i1 = 0; float v1 = s[0];
#pragma unroll
        for (int e = 1; e < E_DIM; e++) if (s[e] > v1) { v1 = s[e]; i1 = e; }
        int i2 = -1; float v2 = -INFINITY;
#pragma unroll
        for (int e = 0; e < E_DIM; e++) if (e != i1 && s[e] > v2) { v2 = s[e]; i2 = e; }
        float sg1 = 1.f / (1.f + expf(-v1));
        float sg2 = 1.f / (1.f + expf(-v2));
        if (writeScores) {
            float* rs = out + (size_t)T_DIM * H_DIM;
#pragma unroll
            for (int e = 0; e < E_DIM; e++)
                rs[(size_t)e * T_DIM + t] = (e == i1) ? sg1 : ((e == i2) ? sg2 : 0.f);
        }
        int p1 = atomicAdd(&g_cnt[i1], 1);
        g_ptok[i1 * T_DIM + p1] = t;
        g_pgp [i1 * T_DIM + p1] = t * 2;
        g_pscl[i1 * T_DIM + p1] = sg1;
        int p2 = atomicAdd(&g_cnt[i2], 1);
        g_ptok[i2 * T_DIM + p2] = t;
        g_pgp [i2 * T_DIM + p2] = t * 2 + 1;
        g_pscl[i2 * T_DIM + p2] = sg2;
    }
}

// ---------------- TF32 mma.sync GEMM (NT, pre-rounded, k-permuted operands) ----------------
// C[m, n] = sum_k A[m, k] * B[n, k]; A, B row-major with row stride = K.
// mode bits: 1 = gather A rows via idxA, 2 = scatter C rows via idxC,
//            4 = scale output rows by sclA, 8 = atomicAdd into C
#define BM 128
#define BN 256
#define BK 32
#define AST 36
#define A_TILE_F (BM * AST)      // 4608
#define B_TILE_F (BN * AST)      // 9216
#define STAGE_F (A_TILE_F + B_TILE_F)
#define NSTAGE 3
#define DYN_SMEM (NSTAGE * STAGE_F * 4)   // 165888

__global__ void __launch_bounds__(256, 1)
gemm_tf32(const float* __restrict__ A, const float* __restrict__ B,
          float* __restrict__ C,
          int M, int N, int K, int ldc, int mode,
          const int* __restrict__ idxA, const int* __restrict__ idxC,
          const float* __restrict__ sclA, const int* __restrict__ cntArr,
          size_t bStride)
{
    extern __shared__ float smem[];
    __shared__ int   s_rowA[BM];
    __shared__ int   s_rowC[BM];
    __shared__ float s_scl [BM];

    const int e = blockIdx.z;
    const int mLim = cntArr ? cntArr[e] : M;
    const int m0 = blockIdx.y * BM;
    if (m0 >= mLim) return;
    const int n0 = blockIdx.x * BN;
    const int nThis = min(BN, N - n0);
    const int lb = e * T_DIM;
    const float* Bp = B + (size_t)e * bStride;

    const int tid = threadIdx.x, lane = tid & 31, warp = tid >> 5;
    const int wm = (warp & 1) * 64, wn = (warp >> 1) * 64;
    const int gid = lane >> 2, tig = lane & 3;
    const int numK = K / BK;

    uint32_t sbase = (uint32_t)__cvta_generic_to_shared(smem);

    if (mode & 1) {
        for (int i = tid; i < BM; i += 256) {
            int ml = min(m0 + i, mLim - 1);
            s_rowA[i] = idxA[lb + ml];
        }
    }
    if (mode & 2) {
        for (int i = tid; i < BM; i += 256) {
            int ml = min(m0 + i, mLim - 1);
            s_rowC[i] = idxC[lb + ml];
            s_scl[i] = (mode & 4) ? sclA[lb + ml] : 1.f;
        }
    }
    if (mode & 3) __syncthreads();

    float acc[4][8][4];
#pragma unroll
    for (int a = 0; a < 4; a++)
#pragma unroll
        for (int b = 0; b < 8; b++)
#pragma unroll
            for (int c = 0; c < 4; c++) acc[a][b][c] = 0.f;

    auto issue_loads = [&](int kt) {
        int st = kt % NSTAGE;
        uint32_t aB = sbase + st * STAGE_F * 4;
        uint32_t bB = aB + A_TILE_F * 4;
        const float* Acol = A + (size_t)kt * BK;
#pragma unroll
        for (int i = 0; i < 4; i++) {
            int cc = tid + i * 256;
            int r = cc >> 3, kc = cc & 7;
            int gm = (mode & 1) ? s_rowA[r] : m0 + r;
            cpasync16(aB + (r * AST + kc * 4) * 4,
                      Acol + (size_t)gm * K + kc * 4);
        }
        const float* Bcol = Bp + (size_t)kt * BK;
#pragma unroll
        for (int i = 0; i < 8; i++) {
            int cc = tid + i * 256;
            int r = cc >> 3, kc = cc & 7;
            if (r < nThis)
                cpasync16(bB + (r * AST + kc * 4) * 4,
                          Bcol + (size_t)(n0 + r) * K + kc * 4);
        }
        asm volatile("cp.async.commit_group;");
    };

#pragma unroll
    for (int kt = 0; kt < NSTAGE; kt++) issue_loads(kt);

    for (int kt = 0; kt < numK; kt++) {
        int st = kt % NSTAGE;
        asm volatile("cp.async.wait_group %0;" :: "n"(NSTAGE - 1));
        __syncthreads();
        const float* As = smem + st * STAGE_F;
        const float* Bs = As + A_TILE_F;
#pragma unroll
        for (int ks = 0; ks < 4; ks++) {
            const int kc = ks * 8 + 2 * tig;  // permuted: holds logical (tig, tig+4)
            uint32_t af[4][4];
#pragma unroll
            for (int mt = 0; mt < 4; mt++) {
                float2 v0 = *(const float2*)&As[(wm + mt * 16 + gid) * AST + kc];
                float2 v1 = *(const float2*)&As[(wm + mt * 16 + 8 + gid) * AST + kc];
                af[mt][0] = __float_as_uint(v0.x);
                af[mt][1] = __float_as_uint(v1.x);
                af[mt][2] = __float_as_uint(v0.y);
                af[mt][3] = __float_as_uint(v1.y);
            }
            uint32_t bf[8][2];
#pragma unroll
            for (int nt = 0; nt < 8; nt++) {
                float2 b = *(const float2*)&Bs[(wn + nt * 8 + gid) * AST + kc];
                bf[nt][0] = __float_as_uint(b.x);
                bf[nt][1] = __float_as_uint(b.y);
            }
#pragma unroll
            for (int mt = 0; mt < 4; mt++)
#pragma unroll
                for (int nt = 0; nt < 8; nt++) {
                    asm volatile(
                        "mma.sync.aligned.m16n8k8.row.col.f32.tf32.tf32.f32 "
                        "{%0,%1,%2,%3}, {%4,%5,%6,%7}, {%8,%9}, {%0,%1,%2,%3};"
                        : "+f"(acc[mt][nt][0]), "+f"(acc[mt][nt][1]),
                          "+f"(acc[mt][nt][2]), "+f"(acc[mt][nt][3])
                        : "r"(af[mt][0]), "r"(af[mt][1]), "r"(af[mt][2]), "r"(af[mt][3]),
                          "r"(bf[nt][0]), "r"(bf[nt][1]));
                }
        }
        __syncthreads();
        if (kt + NSTAGE < numK) issue_loads(kt + NSTAGE);
        else asm volatile("cp.async.commit_group;");
    }

    // epilogue
#pragma unroll
    for (int mt = 0; mt < 4; mt++) {
#pragma unroll
        for (int rr = 0; rr < 2; rr++) {
            int ml  = wm + mt * 16 + gid + rr * 8;
            int gml = m0 + ml;
            if (gml >= mLim) continue;
            float* crow;
            float sc = 1.f;
            if (mode & 2) {
                crow = C + (size_t)s_rowC[ml] * ldc;
                sc = s_scl[ml];
            } else {
                crow = C + (size_t)gml * ldc;
            }
#pragma unroll
            for (int nt = 0; nt < 8; nt++) {
                int cn = n0 + wn + nt * 8 + tig * 2;
                if (cn >= n0 + nThis) continue;
                float v0 = acc[mt][nt][rr * 2 + 0] * sc;
                float v1 = acc[mt][nt][rr * 2 + 1] * sc;
                if (mode & 8) {
                    atomicAdd(crow + cn, v0);
                    atomicAdd(crow + cn + 1, v1);
                } else {
                    *(float2*)(crow + cn) = make_float2(v0, v1);
                }
            }
        }
    }
}

// ---------------- launch ----------------
extern "C" void kernel_launch(void* const* d_in, const int* in_sizes, int n_in,
                              void* d_out, int out_size) {
    const float* x   = (const float*)d_in[0];
    const float* rw  = (const float*)d_in[1];
    const float* gup = (const float*)d_in[2];
    const float* dwn = (const float*)d_in[3];
    const float* sg  = (const float*)d_in[4];
    const float* su  = (const float*)d_in[5];
    const float* sd  = (const float*)d_in[6];
    float* out = (float*)d_out;

    void* p;
    cudaGetSymbolAddress(&p, g_rx);    float* rx   = (float*)p;
    cudaGetSymbolAddress(&p, g_wsgu);  float* wsgu = (float*)p;
    cudaGetSymbolAddress(&p, g_rsd);   float* rsd  = (float*)p;
    cudaGetSymbolAddress(&p, g_gupT);  float* gupT = (float*)p;
    cudaGetSymbolAddress(&p, g_dwnT);  float* dwnT = (float*)p;
    cudaGetSymbolAddress(&p, g_gus);   float* gus  = (float*)p;
    cudaGetSymbolAddress(&p, g_acts);  float* acts = (float*)p;
    cudaGetSymbolAddress(&p, g_gur);   float* gur  = (float*)p;
    cudaGetSymbolAddress(&p, g_actr);  float* actr = (float*)p;
    cudaGetSymbolAddress(&p, g_ptok);  const int* tok = (const int*)p;
    cudaGetSymbolAddress(&p, g_pgp);   const int* gp  = (const int*)p;
    cudaGetSymbolAddress(&p, g_pscl);  const float* psc = (const float*)p;
    cudaGetSymbolAddress(&p, g_cnt);   const int* cnt = (const int*)p;

    cudaFuncSetAttribute(gemm_tf32, cudaFuncAttributeMaxDynamicSharedMemorySize, DYN_SMEM);

    int writeScores = (out_size >= T_DIM * H_DIM + E_DIM * T_DIM) ? 1 : 0;

    zero_cnt_kernel<<<1, 32>>>();
    router_kernel<<<T_DIM / 8, 256>>>(x, rw, out, writeScores);

    // prepass: round + k-permute (and transpose) all GEMM operands
    round_perm_copy<<<2048, 256>>>((const float4*)x,  (float4*)rx,
                                   (long)T_DIM * H_DIM / 8);
    round_perm_copy<<<2048, 256>>>((const float4*)sg, (float4*)wsgu,
                                   (long)I_DIM * H_DIM / 8);
    round_perm_copy<<<2048, 256>>>((const float4*)su,
                                   (float4*)(wsgu + (size_t)I_DIM * H_DIM),
                                   (long)I_DIM * H_DIM / 8);
    round_perm_copy<<<2048, 256>>>((const float4*)sd, (float4*)rsd,
                                   (long)H_DIM * I_DIM / 8);
    transpose_round_perm<<<dim3(GU_DIM / 32, H_DIM / 32, E_DIM), 256>>>(
        gup, gupT, H_DIM, GU_DIM);
    transpose_round_perm<<<dim3(H_DIM / 32, I_DIM / 32, E_DIM), 256>>>(
        dwn, dwnT, I_DIM, H_DIM);

    // GEMM1: gu_s[T, 5760] = rx @ wsgu^T
    gemm_tf32<<<dim3((GU_DIM + BN - 1) / BN, T_DIM / BM, 1), 256, DYN_SMEM>>>(
        rx, wsgu, gus, T_DIM, GU_DIM, H_DIM, GU_DIM, 0,
        nullptr, nullptr, nullptr, nullptr, 0);

    act_perm_kernel<<<2048, 256>>>(gus, acts, T_DIM);

    // GEMM2: out[T, H] = act_s @ rsd^T
    gemm_tf32<<<dim3(H_DIM / BN, T_DIM / BM, 1), 256, DYN_SMEM>>>(
        acts, rsd, out, T_DIM, H_DIM, I_DIM, H_DIM, 0,
        nullptr, nullptr, nullptr, nullptr, 0);

    // GEMM3: gu_r[gp, 5760] = score * (rx[tok] @ gupT[e]^T)
    gemm_tf32<<<dim3((GU_DIM + BN - 1) / BN, T_DIM / BM, E_DIM), 256, DYN_SMEM>>>(
        rx, gupT, gur, T_DIM, GU_DIM, H_DIM, GU_DIM, 1 | 2 | 4,
        tok, gp, psc, cnt, (size_t)GU_DIM * H_DIM);

    act_perm_kernel<<<2048, 256>>>(gur, actr, 2 * T_DIM);

    // GEMM4: out[tok, H] += act_r[gp] @ dwnT[e]^T
    gemm_tf32<<<dim3(H_DIM / BN, T_DIM / BM, E_DIM), 256, DYN_SMEM>>>(
        actr, dwnT, out, T_DIM, H_DIM, I_DIM, H_DIM, 1 | 2 | 8,
        gp, tok, nullptr, cnt, (size_t)H_DIM * I_DIM);
}